// round 7
// baseline (speedup 1.0000x reference)
#include <cuda_runtime.h>

// ---------------- problem constants ----------------
#define M_    64
#define IN_   64
#define H_    256
#define B_    4096
#define RT    64          // batch rows per tile
#define NTHR  512         // 16 warps, warp tile 32x32
#define NITER 32          // tiles per CTA (2 CTAs per model)

// ---------------- pre-transposed weight scratch (K-major, tf32-rounded) ----
__device__ float g_W1T[M_ * H_ * IN_];   // [m][n=256][k=64]   4 MB
__device__ float g_W2T[M_ * H_ * H_];    // [m][n=256][k=256] 16 MB

// ---------------- smem byte offsets ----------------
// 128B "k-segment rows": [rows][32 k floats], 16B chunks XOR-swizzled by (row&7)
#define SM_X0   0          // X buf 0 : 2 ksegs x [64][128B] = 16384
#define SM_X1   16384      // X buf 1 : 16384
#define SM_W1   32768      // W1 (resident): 2 ksegs x [256][128B] = 65536
#define SM_H1   98304      // h1 : 8 ksegs x [64][128B] = 65536
#define SM_RING 163840     // W2 ring: 2 slots x 32768 = 65536
#define SM_RED  229376     // red[64][8] = 2048
#define SM_TOT  231424

// ---------------- PTX helpers ----------------
__device__ __forceinline__ unsigned smem_u32(const void* p) {
    unsigned a;
    asm("{ .reg .u64 t; cvta.to.shared.u64 t, %1; cvt.u32.u64 %0, t; }" : "=r"(a) : "l"(p));
    return a;
}
__device__ __forceinline__ float to_tf32(float x) {
    unsigned u;
    asm("cvt.rna.tf32.f32 %0, %1;" : "=r"(u) : "f"(x));
    return __uint_as_float(u);
}
__device__ __forceinline__ void cpa16(unsigned dst, const void* src) {
    asm volatile("cp.async.cg.shared.global [%0], [%1], 16;" :: "r"(dst), "l"(src));
}
#define CP_COMMIT()  asm volatile("cp.async.commit_group;" ::: "memory")
#define CP_WAIT(N)   asm volatile("cp.async.wait_group %0;" :: "n"(N) : "memory")

__device__ __forceinline__ void ldsm4(unsigned addr, unsigned r[4]) {
    asm volatile("ldmatrix.sync.aligned.m8n8.x4.shared.b16 {%0,%1,%2,%3}, [%4];"
        : "=r"(r[0]), "=r"(r[1]), "=r"(r[2]), "=r"(r[3]) : "r"(addr));
}
__device__ __forceinline__ void mma8(float c[4], const unsigned a[4],
                                     unsigned b0, unsigned b1) {
    asm volatile("mma.sync.aligned.m16n8k8.row.col.f32.tf32.tf32.f32 "
        "{%0,%1,%2,%3},{%4,%5,%6,%7},{%8,%9},{%0,%1,%2,%3};"
        : "+f"(c[0]), "+f"(c[1]), "+f"(c[2]), "+f"(c[3])
        : "r"(a[0]), "r"(a[1]), "r"(a[2]), "r"(a[3]), "r"(b0), "r"(b1));
}

// one K=8 step, warp tile 32x32: A rows [m0..m0+32), W rows [n0..n0+32)
__device__ __forceinline__ void kstep(unsigned Aseg, unsigned Wseg, int kl,
                                      int m0, int n0, int lane,
                                      float acc[2][4][4])
{
    const int rin = lane & 7, sub = lane >> 3;
    unsigned a[2][4], b[2][4];
    {
        int chunk = kl * 2 + (sub >> 1);
        int roff  = rin + (sub & 1) * 8;
#pragma unroll
        for (int mt = 0; mt < 2; ++mt) {
            int row = m0 + mt * 16 + roff;
            ldsm4(Aseg + row * 128 + ((chunk ^ (row & 7)) << 4), a[mt]);
        }
    }
    {
        int chunk = kl * 2 + (sub & 1);
        int roff  = rin + (sub >> 1) * 8;
#pragma unroll
        for (int p = 0; p < 2; ++p) {
            int row = n0 + p * 16 + roff;
            ldsm4(Wseg + row * 128 + ((chunk ^ (row & 7)) << 4), b[p]);
        }
    }
#pragma unroll
    for (int mt = 0; mt < 2; ++mt)
#pragma unroll
        for (int p = 0; p < 2; ++p) {
            mma8(acc[mt][2 * p],     a[mt], b[p][0], b[p][1]);
            mma8(acc[mt][2 * p + 1], a[mt], b[p][2], b[p][3]);
        }
}

// ---------------- merged transpose + tf32-round kernel ----------------
__global__ void transpose_cvt_all(const float* __restrict__ W1,
                                  const float* __restrict__ W2,
                                  float* __restrict__ W1T,
                                  float* __restrict__ W2T)
{
    __shared__ float tile[32][33];
    const int m = blockIdx.z;
    const float* in;
    float* out;
    int K, kt;
    if (blockIdx.y < 2) { in = W1; out = W1T; K = IN_; kt = blockIdx.y; }
    else                { in = W2; out = W2T; K = H_;  kt = blockIdx.y - 2; }
    in  += (size_t)m * K * H_;
    out += (size_t)m * K * H_;
    const int n0 = blockIdx.x * 32, k0 = kt * 32;
    const int tx = threadIdx.x, ty = threadIdx.y;
#pragma unroll
    for (int j = ty; j < 32; j += 8)
        tile[j][tx] = in[(size_t)(k0 + j) * H_ + n0 + tx];
    __syncthreads();
#pragma unroll
    for (int j = ty; j < 32; j += 8)
        out[(size_t)(n0 + j) * K + k0 + tx] = to_tf32(tile[tx][j]);
}

// ---------------- persistent fused MLP kernel ----------------
__global__ __launch_bounds__(NTHR, 1)
void mlp_mma_persistent(const float* __restrict__ xs,
                        const float* __restrict__ b1g,
                        const float* __restrict__ b2g,
                        const float* __restrict__ w3g,
                        const float* __restrict__ b3g,
                        float* __restrict__ out)
{
    extern __shared__ char smem[];
    const unsigned sb = smem_u32(smem);
    const int t    = threadIdx.x;
    const int lane = t & 31;
    const int wid  = t >> 5;
    const int m    = blockIdx.x >> 1;     // fixed model for this CTA
    const int half = blockIdx.x & 1;      // tile range [half*32, half*32+32)
    const int m0   = (wid >> 3) * 32;
    const int n0   = (wid & 7) * 32;
    const int g    = lane >> 2;
    const int tg   = lane & 3;

    const float* w2m = g_W2T + (size_t)m * H_ * H_;
    const float* xm  = xs + (size_t)m * B_ * IN_;
    float* red = (float*)(smem + SM_RED);

    // ---- Ginit: W1 (resident) + X(tile 0) ----
    {
        const float4* w1s = (const float4*)(g_W1T + (size_t)m * H_ * IN_);
#pragma unroll
        for (int i = 0; i < 8; ++i) {               // 4096 float4
            int idx = t + i * NTHR;
            int row = idx >> 4, c = idx & 15;
            int kseg = c >> 3, cc = c & 7;
            cpa16(sb + SM_W1 + kseg * 32768 + row * 128 + ((cc ^ (row & 7)) << 4),
                  w1s + idx);
        }
        const float4* src = (const float4*)(xm + (size_t)(half * NITER) * RT * IN_);
#pragma unroll
        for (int i = 0; i < 2; ++i) {               // 1024 float4
            int idx = t + i * NTHR;
            int row = idx >> 4, c = idx & 15;
            int kseg = c >> 3, cc = c & 7;
            cpa16(sb + SM_X0 + kseg * 8192 + row * 128 + ((cc ^ (row & 7)) << 4),
                  src + idx);
        }
    }
    CP_COMMIT();
    // ---- W2 chunk 0 -> ring slot 0 ----
#pragma unroll
    for (int i = 0; i < 4; ++i) {                   // 2048 float4
        int idx = t + i * NTHR;
        int n = idx >> 3, c = idx & 7;
        cpa16(sb + SM_RING + n * 128 + ((c ^ (n & 7)) << 4),
              (const float4*)(w2m + n * H_) + c);
    }
    CP_COMMIT();
    CP_WAIT(1);       // Ginit done (chunk 0 may still be in flight)
    __syncthreads();

    float acc[2][4][4];

    for (int it = 0; it < NITER; ++it) {
        const unsigned Xb = sb + ((it & 1) ? SM_X1 : SM_X0);

#pragma unroll
        for (int mt = 0; mt < 2; ++mt)
#pragma unroll
            for (int nt = 0; nt < 4; ++nt)
#pragma unroll
                for (int j = 0; j < 4; ++j) acc[mt][nt][j] = 0.f;

        // ---- layer 1: K=64, 8 ksteps (W1 resident) ----
#pragma unroll
        for (int s = 0; s < 8; ++s)
            kstep(Xb + (s >> 2) * 8192, sb + SM_W1 + (s >> 2) * 32768,
                  s & 3, m0, n0, lane, acc);

        // ---- epilogue 1: h1 = tf32(relu(acc + b1)) -> SM_H1 ----
#pragma unroll
        for (int nt = 0; nt < 4; ++nt) {
            int col = n0 + nt * 8 + 2 * tg;
            float2 bb = __ldg((const float2*)(b1g + m * H_ + col));
            int kseg = col >> 5, colin = col & 31;
            int chunk = colin >> 2, within = colin & 3;
#pragma unroll
            for (int mt = 0; mt < 2; ++mt) {
                float* c = acc[mt][nt];
#pragma unroll
                for (int h = 0; h < 2; ++h) {
                    int row = m0 + mt * 16 + g + h * 8;
                    float2 v;
                    v.x = to_tf32(fmaxf(c[2 * h]     + bb.x, 0.f));
                    v.y = to_tf32(fmaxf(c[2 * h + 1] + bb.y, 0.f));
                    *(float2*)(smem + SM_H1 + kseg * 8192 + row * 128 +
                               ((chunk ^ (row & 7)) << 4) + within * 4) = v;
                }
            }
        }
#pragma unroll
        for (int mt = 0; mt < 2; ++mt)
#pragma unroll
            for (int nt = 0; nt < 4; ++nt)
#pragma unroll
                for (int j = 0; j < 4; ++j) acc[mt][nt][j] = 0.f;

        // ---- layer 2: 8 chunks, 2-slot ring, continuous across iterations ----
#pragma unroll
        for (int kb = 0; kb < 8; ++kb) {
            CP_WAIT(0);        // chunk kb (and anything older) landed
            __syncthreads();   // visibility + slot/H1 reuse barrier
            if (kb == 0 && it + 1 < NITER) {
                // prefetch X(it+1) into the other X buffer
                const float4* src = (const float4*)
                    (xm + (size_t)(half * NITER + it + 1) * RT * IN_);
                unsigned dstb = sb + (((it + 1) & 1) ? SM_X1 : SM_X0);
#pragma unroll
                for (int i = 0; i < 2; ++i) {
                    int idx = t + i * NTHR;
                    int row = idx >> 4, c = idx & 15;
                    int kseg = c >> 3, cc = c & 7;
                    cpa16(dstb + kseg * 8192 + row * 128 + ((cc ^ (row & 7)) << 4),
                          src + idx);
                }
                CP_COMMIT();
            }
            if (!(it == NITER - 1 && kb == 7)) {
                // prefetch next chunk (wraps to chunk 0 of next iteration)
                const int nkb = (kb + 1) & 7;
#pragma unroll
                for (int i = 0; i < 4; ++i) {
                    int idx = t + i * NTHR;
                    int n = idx >> 3, c = idx & 7;
                    cpa16(sb + SM_RING + (nkb & 1) * 32768 + n * 128 +
                              ((c ^ (n & 7)) << 4),
                          (const float4*)(w2m + n * H_ + nkb * 32) + c);
                }
                CP_COMMIT();
            }
            unsigned Aseg = sb + SM_H1 + kb * 8192;
            unsigned Wseg = sb + SM_RING + (kb & 1) * 32768;
#pragma unroll
            for (int ls = 0; ls < 4; ++ls)
                kstep(Aseg, Wseg, ls, m0, n0, lane, acc);
        }

        // ---- epilogue 2: out = relu(acc + b2) . w3 + b3 ----
        {
            float part[2][2] = {{0.f, 0.f}, {0.f, 0.f}};
#pragma unroll
            for (int nt = 0; nt < 4; ++nt) {
                int col = n0 + nt * 8 + 2 * tg;
                float2 bb = __ldg((const float2*)(b2g + m * H_ + col));
                float2 ww = __ldg((const float2*)(w3g + m * H_ + col));
#pragma unroll
                for (int mt = 0; mt < 2; ++mt) {
                    float* c = acc[mt][nt];
                    part[mt][0] = fmaf(fmaxf(c[0] + bb.x, 0.f), ww.x, part[mt][0]);
                    part[mt][0] = fmaf(fmaxf(c[1] + bb.y, 0.f), ww.y, part[mt][0]);
                    part[mt][1] = fmaf(fmaxf(c[2] + bb.x, 0.f), ww.x, part[mt][1]);
                    part[mt][1] = fmaf(fmaxf(c[3] + bb.y, 0.f), ww.y, part[mt][1]);
                }
            }
#pragma unroll
            for (int sfl = 1; sfl < 4; sfl <<= 1)
#pragma unroll
                for (int mt = 0; mt < 2; ++mt) {
                    part[mt][0] += __shfl_xor_sync(0xffffffffu, part[mt][0], sfl);
                    part[mt][1] += __shfl_xor_sync(0xffffffffu, part[mt][1], sfl);
                }
            if (tg == 0) {
#pragma unroll
                for (int mt = 0; mt < 2; ++mt) {
                    red[(m0 + mt * 16 + g) * 8     + (wid & 7)] = part[mt][0];
                    red[(m0 + mt * 16 + g + 8) * 8 + (wid & 7)] = part[mt][1];
                }
            }
            __syncthreads();   // also guarantees all warps done with H1/chunk 7
            if (t < RT) {
                const float* r = red + t * 8;
                float s = ((r[0] + r[1]) + (r[2] + r[3])) +
                          ((r[4] + r[5]) + (r[6] + r[7]));
                out[(size_t)m * B_ + (size_t)(half * NITER + it) * RT + t] =
                    s + __ldg(b3g + m);
            }
        }
    }
}

// ---------------- launcher ----------------
extern "C" void kernel_launch(void* const* d_in, const int* in_sizes, int n_in,
                              void* d_out, int out_size)
{
    const float* xs = (const float*)d_in[0];
    const float* W1 = (const float*)d_in[1];
    const float* b1 = (const float*)d_in[2];
    const float* W2 = (const float*)d_in[3];
    const float* b2 = (const float*)d_in[4];
    const float* W3 = (const float*)d_in[5];
    const float* b3 = (const float*)d_in[6];
    float* out = (float*)d_out;

    void* p1 = nullptr; void* p2 = nullptr;
    cudaGetSymbolAddress(&p1, g_W1T);
    cudaGetSymbolAddress(&p2, g_W2T);

    dim3 tb(32, 8);
    transpose_cvt_all<<<dim3(H_ / 32, 10, M_), tb>>>(W1, W2, (float*)p1, (float*)p2);

    cudaFuncSetAttribute(mlp_mma_persistent,
                         cudaFuncAttributeMaxDynamicSharedMemorySize, SM_TOT);
    mlp_mma_persistent<<<2 * M_, NTHR, SM_TOT>>>(xs, b1, b2, W3, b3, out);
}

// round 9
// speedup vs baseline: 1.3371x; 1.3371x over previous
#include <cuda_runtime.h>

// ---------------- problem constants ----------------
#define M_    64
#define IN_   64
#define H_    256
#define B_    4096
#define RT    64          // batch rows per tile
#define NTHR  512         // 16 warps, warp tile 32x32
#define NCTA  148
#define NTILE 4096        // model-major: tile tt -> model tt>>6, rows (tt&63)*64

// ---------------- pre-transposed weight scratch (K-major, tf32-rounded) ----
__device__ float g_W1T[M_ * H_ * IN_];   // [m][n=256][k=64]   4 MB
__device__ float g_W2T[M_ * H_ * H_];    // [m][n=256][k=256] 16 MB

// ---------------- smem byte offsets ----------------
// 128B "k-segment rows": [rows][32 k floats], 16B chunks XOR-swizzled by (row&7)
#define SM_X0   0          // X buf 0 : 2 ksegs x [64][128B] = 16384
#define SM_X1   16384
#define SM_W1   32768      // W1 resident: 2 ksegs x [256][128B] = 65536
#define SM_H1   98304      // h1 : 8 ksegs x [64][128B] = 65536
#define SM_RING 163840     // W2 ring: 2 slots x 32768 (4 half-positions of 16 KB)
#define SM_RED  229376     // red[64][8]
#define SM_TOT  231424

// ---------------- PTX helpers ----------------
__device__ __forceinline__ unsigned smem_u32(const void* p) {
    unsigned a;
    asm("{ .reg .u64 t; cvta.to.shared.u64 t, %1; cvt.u32.u64 %0, t; }" : "=r"(a) : "l"(p));
    return a;
}
__device__ __forceinline__ float to_tf32(float x) {
    unsigned u;
    asm("cvt.rna.tf32.f32 %0, %1;" : "=r"(u) : "f"(x));
    return __uint_as_float(u);
}
__device__ __forceinline__ void cpa16(unsigned dst, const void* src) {
    asm volatile("cp.async.cg.shared.global [%0], [%1], 16;" :: "r"(dst), "l"(src));
}
#define CP_COMMIT()  asm volatile("cp.async.commit_group;" ::: "memory")
#define CP_WAIT(N)   asm volatile("cp.async.wait_group %0;" :: "n"(N) : "memory")

__device__ __forceinline__ void ldsm4(unsigned addr, unsigned r[4]) {
    asm volatile("ldmatrix.sync.aligned.m8n8.x4.shared.b16 {%0,%1,%2,%3}, [%4];"
        : "=r"(r[0]), "=r"(r[1]), "=r"(r[2]), "=r"(r[3]) : "r"(addr));
}
__device__ __forceinline__ void mma8(float c[4], const unsigned a[4],
                                     unsigned b0, unsigned b1) {
    asm volatile("mma.sync.aligned.m16n8k8.row.col.f32.tf32.tf32.f32 "
        "{%0,%1,%2,%3},{%4,%5,%6,%7},{%8,%9},{%0,%1,%2,%3};"
        : "+f"(c[0]), "+f"(c[1]), "+f"(c[2]), "+f"(c[3])
        : "r"(a[0]), "r"(a[1]), "r"(a[2]), "r"(a[3]), "r"(b0), "r"(b1));
}

// one K=8 step, warp tile 32x32: A rows [m0..m0+32), W rows [n0..n0+32)
__device__ __forceinline__ void kstep(unsigned Aseg, unsigned Wseg, int kl,
                                      int m0, int n0, int lane,
                                      float acc[2][4][4])
{
    const int rin = lane & 7, sub = lane >> 3;
    unsigned a[2][4], b[2][4];
    {
        int chunk = kl * 2 + (sub >> 1);
        int roff  = rin + (sub & 1) * 8;
#pragma unroll
        for (int mt = 0; mt < 2; ++mt) {
            int row = m0 + mt * 16 + roff;
            ldsm4(Aseg + row * 128 + ((chunk ^ (row & 7)) << 4), a[mt]);
        }
    }
    {
        int chunk = kl * 2 + (sub & 1);
        int roff  = rin + (sub >> 1) * 8;
#pragma unroll
        for (int p = 0; p < 2; ++p) {
            int row = n0 + p * 16 + roff;
            ldsm4(Wseg + row * 128 + ((chunk ^ (row & 7)) << 4), b[p]);
        }
    }
#pragma unroll
    for (int mt = 0; mt < 2; ++mt)
#pragma unroll
        for (int p = 0; p < 2; ++p) {
            mma8(acc[mt][2 * p],     a[mt], b[p][0], b[p][1]);
            mma8(acc[mt][2 * p + 1], a[mt], b[p][2], b[p][3]);
        }
}

// prefetch one 16-KB W2 k-half: chunk kb (0..7), half (0..1) of model base w2m
__device__ __forceinline__ void prefetch_half(unsigned sb, const float* w2m,
                                              int kb, int half, int t)
{
#pragma unroll
    for (int i = 0; i < 2; ++i) {            // 1024 float4
        int idx = t + i * NTHR;
        int n  = idx >> 2;                    // 0..255
        int c4 = idx & 3;                     // 0..3
        int c  = c4 + half * 4;               // column 0..7 within 128B row
        cpa16(sb + SM_RING + (kb & 1) * 32768 + n * 128 +
                  ((unsigned)(c ^ (n & 7)) << 4),
              (const float4*)(w2m + n * H_) + kb * 8 + half * 4 + c4);
    }
}
__device__ __forceinline__ void prefetch_X(unsigned dstb, const float* src, int t)
{
#pragma unroll
    for (int i = 0; i < 2; ++i) {            // 1024 float4
        int idx = t + i * NTHR;
        int row = idx >> 4, c = idx & 15;
        int kseg = c >> 3, cc = c & 7;
        cpa16(dstb + kseg * 8192 + row * 128 + ((cc ^ (row & 7)) << 4),
              (const float4*)src + idx);
    }
}
__device__ __forceinline__ void load_W1(unsigned sb, const float* w1m, int t)
{
#pragma unroll
    for (int i = 0; i < 8; ++i) {            // 4096 float4
        int idx = t + i * NTHR;
        int row = idx >> 4, c = idx & 15;
        int kseg = c >> 3, cc = c & 7;
        cpa16(sb + SM_W1 + kseg * 32768 + row * 128 + ((cc ^ (row & 7)) << 4),
              (const float4*)w1m + idx);
    }
}

// ---------------- merged transpose + tf32-round kernel ----------------
__global__ void transpose_cvt_all(const float* __restrict__ W1,
                                  const float* __restrict__ W2,
                                  float* __restrict__ W1T,
                                  float* __restrict__ W2T)
{
    __shared__ float tile[32][33];
    const int m = blockIdx.z;
    const float* in;
    float* out;
    int K, kt;
    if (blockIdx.y < 2) { in = W1; out = W1T; K = IN_; kt = blockIdx.y; }
    else                { in = W2; out = W2T; K = H_;  kt = blockIdx.y - 2; }
    in  += (size_t)m * K * H_;
    out += (size_t)m * K * H_;
    const int n0 = blockIdx.x * 32, k0 = kt * 32;
    const int tx = threadIdx.x, ty = threadIdx.y;
#pragma unroll
    for (int j = ty; j < 32; j += 8)
        tile[j][tx] = in[(size_t)(k0 + j) * H_ + n0 + tx];
    __syncthreads();
#pragma unroll
    for (int j = ty; j < 32; j += 8)
        out[(size_t)(n0 + j) * K + k0 + tx] = to_tf32(tile[tx][j]);
}

// ---------------- persistent fused MLP kernel ----------------
__global__ __launch_bounds__(NTHR, 1)
void mlp_mma_persistent(const float* __restrict__ xs,
                        const float* __restrict__ b1g,
                        const float* __restrict__ b2g,
                        const float* __restrict__ w3g,
                        const float* __restrict__ b3g,
                        float* __restrict__ out)
{
    extern __shared__ char smem[];
    const unsigned sb = smem_u32(smem);
    const int t    = threadIdx.x;
    const int lane = t & 31;
    const int wid  = t >> 5;
    const int m0   = (wid >> 3) * 32;
    const int n0   = (wid & 7) * 32;
    const int g    = lane >> 2;
    const int tg   = lane & 3;

    // contiguous tile range [t0, t1) in model-major order
    const int t0 = (blockIdx.x * 1024) / 37;        // *4096/148
    const int t1 = ((blockIdx.x + 1) * 1024) / 37;
    float* red = (float*)(smem + SM_RED);

    int cur_model = t0 >> 6;

    // ---- prologue: G(W1+X0), then halves (t0,0..2) ----
    load_W1(sb, g_W1T + (size_t)cur_model * H_ * IN_, t);
    prefetch_X(sb + ((t0 & 1) ? SM_X1 : SM_X0), xs + (size_t)t0 * RT * IN_, t);
    CP_COMMIT();
    {
        const float* w2m = g_W2T + (size_t)cur_model * H_ * H_;
#pragma unroll
        for (int p = 0; p < 3; ++p) {
            prefetch_half(sb, w2m, p >> 1, p & 1, t);
            CP_COMMIT();
        }
    }
    CP_WAIT(3);
    __syncthreads();

    float acc[2][4][4];

    for (int tt = t0; tt < t1; ++tt) {
        const int model = tt >> 6;
        const bool last_tile = (tt == t1 - 1);
        if (model != cur_model) {
            // flush + W1 reload (once per CTA at most)
            CP_WAIT(0);
            __syncthreads();
            load_W1(sb, g_W1T + (size_t)model * H_ * IN_, t);
            CP_COMMIT();
            CP_WAIT(0);
            __syncthreads();
            cur_model = model;
        }
        const unsigned Xb = sb + ((tt & 1) ? SM_X1 : SM_X0);

#pragma unroll
        for (int mt = 0; mt < 2; ++mt)
#pragma unroll
            for (int nt = 0; nt < 4; ++nt)
#pragma unroll
                for (int j = 0; j < 4; ++j) acc[mt][nt][j] = 0.f;

        // ---- layer 1: K=64, 8 ksteps (W1 resident) ----
#pragma unroll
        for (int s = 0; s < 8; ++s)
            kstep(Xb + (s >> 2) * 8192, sb + SM_W1 + (s >> 2) * 32768,
                  s & 3, m0, n0, lane, acc);

        // ---- epilogue 1: h1 = tf32(relu(acc + b1)) -> SM_H1 ----
#pragma unroll
        for (int nt = 0; nt < 4; ++nt) {
            int col = n0 + nt * 8 + 2 * tg;
            float2 bb = __ldg((const float2*)(b1g + model * H_ + col));
            int kseg = col >> 5, colin = col & 31;
            int chunk = colin >> 2, within = colin & 3;
#pragma unroll
            for (int mt = 0; mt < 2; ++mt) {
                float* c = acc[mt][nt];
#pragma unroll
                for (int h = 0; h < 2; ++h) {
                    int row = m0 + mt * 16 + g + h * 8;
                    float2 v;
                    v.x = to_tf32(fmaxf(c[2 * h]     + bb.x, 0.f));
                    v.y = to_tf32(fmaxf(c[2 * h + 1] + bb.y, 0.f));
                    *(float2*)(smem + SM_H1 + kseg * 8192 + row * 128 +
                               ((chunk ^ (row & 7)) << 4) + within * 4) = v;
                }
            }
        }
#pragma unroll
        for (int mt = 0; mt < 2; ++mt)
#pragma unroll
            for (int nt = 0; nt < 4; ++nt)
#pragma unroll
                for (int j = 0; j < 4; ++j) acc[mt][nt][j] = 0.f;

        // ---- layer 2: 16 halves, 4-position ring, distance-3 prefetch ----
        for (int hh = 0; hh < 16; ++hh) {
            if (!last_tile || hh < 14) { CP_WAIT(2); }
            else if (hh == 14)         { CP_WAIT(1); }
            else                       { CP_WAIT(0); }
            __syncthreads();   // half hh visible to all; position (hh+3)&3 free

            // prefetch half (tt, hh+3) [wraps into next tile]; fold X at hh==0
            {
                int ptt = tt, phh = hh + 3;
                if (phh >= 16) { phh -= 16; ++ptt; }
                if (ptt < t1) {
                    prefetch_half(sb, g_W2T + (size_t)(ptt >> 6) * H_ * H_,
                                  phh >> 1, phh & 1, t);
                    if (hh == 0 && tt + 1 < t1)
                        prefetch_X(sb + (((tt + 1) & 1) ? SM_X1 : SM_X0),
                                   xs + (size_t)(tt + 1) * RT * IN_, t);
                    CP_COMMIT();
                }
            }
            const int kb = hh >> 1;
            const unsigned Aseg = sb + SM_H1 + kb * 8192;
            const unsigned Wseg = sb + SM_RING + (kb & 1) * 32768;
            const int kl0 = (hh & 1) * 2;
            kstep(Aseg, Wseg, kl0,     m0, n0, lane, acc);
            kstep(Aseg, Wseg, kl0 + 1, m0, n0, lane, acc);
        }

        // ---- epilogue 2: out = relu(acc + b2) . w3 + b3 ----
        {
            float part[2][2] = {{0.f, 0.f}, {0.f, 0.f}};
#pragma unroll
            for (int nt = 0; nt < 4; ++nt) {
                int col = n0 + nt * 8 + 2 * tg;
                float2 bb = __ldg((const float2*)(b2g + model * H_ + col));
                float2 ww = __ldg((const float2*)(w3g + model * H_ + col));
#pragma unroll
                for (int mt = 0; mt < 2; ++mt) {
                    float* c = acc[mt][nt];
                    part[mt][0] = fmaf(fmaxf(c[0] + bb.x, 0.f), ww.x, part[mt][0]);
                    part[mt][0] = fmaf(fmaxf(c[1] + bb.y, 0.f), ww.y, part[mt][0]);
                    part[mt][1] = fmaf(fmaxf(c[2] + bb.x, 0.f), ww.x, part[mt][1]);
                    part[mt][1] = fmaf(fmaxf(c[3] + bb.y, 0.f), ww.y, part[mt][1]);
                }
            }
#pragma unroll
            for (int sfl = 1; sfl < 4; sfl <<= 1)
#pragma unroll
                for (int mt = 0; mt < 2; ++mt) {
                    part[mt][0] += __shfl_xor_sync(0xffffffffu, part[mt][0], sfl);
                    part[mt][1] += __shfl_xor_sync(0xffffffffu, part[mt][1], sfl);
                }
            if (tg == 0) {
#pragma unroll
                for (int mt = 0; mt < 2; ++mt) {
                    red[(m0 + mt * 16 + g) * 8     + (wid & 7)] = part[mt][0];
                    red[(m0 + mt * 16 + g + 8) * 8 + (wid & 7)] = part[mt][1];
                }
            }
            __syncthreads();   // red ready; all warps done with H1 / last half
            if (t < RT) {
                const float* r = red + t * 8;
                float s = ((r[0] + r[1]) + (r[2] + r[3])) +
                          ((r[4] + r[5]) + (r[6] + r[7]));
                out[(size_t)tt * RT + t] = s + __ldg(b3g + model);
            }
        }
    }
}

// ---------------- launcher ----------------
extern "C" void kernel_launch(void* const* d_in, const int* in_sizes, int n_in,
                              void* d_out, int out_size)
{
    const float* xs = (const float*)d_in[0];
    const float* W1 = (const float*)d_in[1];
    const float* b1 = (const float*)d_in[2];
    const float* W2 = (const float*)d_in[3];
    const float* b2 = (const float*)d_in[4];
    const float* W3 = (const float*)d_in[5];
    const float* b3 = (const float*)d_in[6];
    float* out = (float*)d_out;

    void* p1 = nullptr; void* p2 = nullptr;
    cudaGetSymbolAddress(&p1, g_W1T);
    cudaGetSymbolAddress(&p2, g_W2T);

    dim3 tb(32, 8);
    transpose_cvt_all<<<dim3(H_ / 32, 10, M_), tb>>>(W1, W2, (float*)p1, (float*)p2);

    cudaFuncSetAttribute(mlp_mma_persistent,
                         cudaFuncAttributeMaxDynamicSharedMemorySize, SM_TOT);
    mlp_mma_persistent<<<NCTA, NTHR, SM_TOT>>>(xs, b1, b2, W3, b3, out);
}

// round 10
// speedup vs baseline: 1.9584x; 1.4647x over previous
#include <cuda_runtime.h>
#include <cuda_fp16.h>

// ---------------- problem constants ----------------
#define M_   64
#define IN_  64
#define H_   256
#define B_   4096
#define RT   64           // batch rows per CTA
#define NTHR 256          // 8 warps: grid 2m x 4n, warp tile 32x64

// ---------------- fp16 scratch (K-major weights, converted x) ----------------
__device__ __align__(16) __half g_W1Th[M_ * H_ * IN_];   // [m][n=256][k=64]   2 MB
__device__ __align__(16) __half g_W2Th[M_ * H_ * H_];    // [m][n=256][k=256]  8 MB
__device__ __align__(16) __half g_Xh[(size_t)M_ * B_ * IN_];  // [m][b][k=64]  32 MB

// ---------------- smem byte offsets (fp16 rows: 128B = 64 halves) ----------------
// swizzle: 16B chunk c of row r -> c ^ (r & 7)
#define SM_X    0          // X [64][128B] = 8192   (dead after layer 1 -> red)
#define SM_W1   8192       // W1 [256][128B] = 32768 (ring slot 1 after layer 1)
#define SM_H1   40960      // h1: 4 ksegs x [64][128B] = 32768
#define SM_RING 73728      // ring slot 0: 32768
#define SM_TOT  106496     // x2 CTAs = 212992 <= carveout
#define SM_RED  SM_X       // red[64][4] floats overlays X

// ---------------- PTX helpers ----------------
__device__ __forceinline__ unsigned smem_u32(const void* p) {
    unsigned a;
    asm("{ .reg .u64 t; cvta.to.shared.u64 t, %1; cvt.u32.u64 %0, t; }" : "=r"(a) : "l"(p));
    return a;
}
__device__ __forceinline__ void cpa16(unsigned dst, const void* src) {
    asm volatile("cp.async.cg.shared.global [%0], [%1], 16;" :: "r"(dst), "l"(src));
}
#define CP_COMMIT()  asm volatile("cp.async.commit_group;" ::: "memory")
#define CP_WAIT(N)   asm volatile("cp.async.wait_group %0;" :: "n"(N) : "memory")

__device__ __forceinline__ void ldsm4(unsigned addr, unsigned r[4]) {
    asm volatile("ldmatrix.sync.aligned.m8n8.x4.shared.b16 {%0,%1,%2,%3}, [%4];"
        : "=r"(r[0]), "=r"(r[1]), "=r"(r[2]), "=r"(r[3]) : "r"(addr));
}
// fp16 m16n8k16, fp32 accumulate
__device__ __forceinline__ void mma16(float c[4], const unsigned a[4],
                                      unsigned b0, unsigned b1) {
    asm volatile("mma.sync.aligned.m16n8k16.row.col.f32.f16.f16.f32 "
        "{%0,%1,%2,%3},{%4,%5,%6,%7},{%8,%9},{%0,%1,%2,%3};"
        : "+f"(c[0]), "+f"(c[1]), "+f"(c[2]), "+f"(c[3])
        : "r"(a[0]), "r"(a[1]), "r"(a[2]), "r"(a[3]), "r"(b0), "r"(b1));
}

// one K=16 step, warp tile 32x64: A rows [m0..m0+32), W rows [n0..n0+64)
// s = k16-step index within a 64-wide k segment (0..3); 16B chunk = 8 fp16
__device__ __forceinline__ void kstep(unsigned Aseg, unsigned Wseg, int s,
                                      int m0, int n0, int lane,
                                      float acc[2][8][4])
{
    const int rin = lane & 7, sub = lane >> 3;
    unsigned a[2][4], b[4][4];
    {   // A x4: (m0-7,k0-7)(m8-15,k0-7)(m0-7,k8-15)(m8-15,k8-15)
        int ch   = 2 * s + (sub >> 1);
        int roff = rin + (sub & 1) * 8;
#pragma unroll
        for (int mt = 0; mt < 2; ++mt) {
            int row = m0 + mt * 16 + roff;
            ldsm4(Aseg + row * 128 + ((ch ^ (row & 7)) << 4), a[mt]);
        }
    }
    {   // B x4 per p: (n0-7,k0-7)(n0-7,k8-15)(n8-15,k0-7)(n8-15,k8-15)
        int ch   = 2 * s + (sub & 1);
        int roff = rin + (sub >> 1) * 8;
#pragma unroll
        for (int p = 0; p < 4; ++p) {
            int row = n0 + p * 16 + roff;
            ldsm4(Wseg + row * 128 + ((ch ^ (row & 7)) << 4), b[p]);
        }
    }
#pragma unroll
    for (int mt = 0; mt < 2; ++mt)
#pragma unroll
        for (int p = 0; p < 4; ++p) {
            mma16(acc[mt][2 * p],     a[mt], b[p][0], b[p][1]);
            mma16(acc[mt][2 * p + 1], a[mt], b[p][2], b[p][3]);
        }
}

// ---------------- prep: transpose weights to K-major fp16 ----------------
__global__ void transpose_cvt_all(const float* __restrict__ W1,
                                  const float* __restrict__ W2,
                                  __half* __restrict__ W1T,
                                  __half* __restrict__ W2T)
{
    __shared__ float tile[32][33];
    const int m = blockIdx.z;
    const float* in;
    __half* out;
    int K, kt;
    if (blockIdx.y < 2) { in = W1; out = W1T; K = IN_; kt = blockIdx.y; }
    else                { in = W2; out = W2T; K = H_;  kt = blockIdx.y - 2; }
    in  += (size_t)m * K * H_;
    out += (size_t)m * K * H_;
    const int n0 = blockIdx.x * 32, k0 = kt * 32;
    const int tx = threadIdx.x, ty = threadIdx.y;
#pragma unroll
    for (int j = ty; j < 32; j += 8)
        tile[j][tx] = in[(size_t)(k0 + j) * H_ + n0 + tx];
    __syncthreads();
#pragma unroll
    for (int j = ty; j < 32; j += 8)
        out[(size_t)(n0 + j) * K + k0 + tx] = __float2half_rn(tile[tx][j]);
}

// ---------------- prep: convert xs to fp16 ----------------
__global__ void convert_x(const float4* __restrict__ in, uint2* __restrict__ out,
                          int n4)
{
    int i = blockIdx.x * blockDim.x + threadIdx.x;
    if (i < n4) {
        float4 v = in[i];
        __half2 h0 = __floats2half2_rn(v.x, v.y);
        __half2 h1 = __floats2half2_rn(v.z, v.w);
        uint2 u;
        u.x = *(unsigned*)&h0;
        u.y = *(unsigned*)&h1;
        out[i] = u;
    }
}

// ---------------- fused MLP kernel (fp16 MMA, 2 CTAs/SM) ----------------
__global__ __launch_bounds__(NTHR, 2)
void mlp_mma_f16(const float* __restrict__ b1g,
                 const float* __restrict__ b2g,
                 const float* __restrict__ w3g,
                 const float* __restrict__ b3g,
                 float* __restrict__ out)
{
    extern __shared__ char smem[];
    const unsigned sb = smem_u32(smem);
    const int t    = threadIdx.x;
    const int lane = t & 31;
    const int wid  = t >> 5;
    const int m    = blockIdx.y;
    const int r0   = blockIdx.x * RT;
    const int m0   = (wid >> 2) * 32;     // warp row base (0 / 32)
    const int n0   = (wid & 3) * 64;      // warp col base (0/64/128/192)
    const int g    = lane >> 2;
    const int tg   = lane & 3;

    const __half* w2m = g_W2Th + (size_t)m * H_ * H_;

    // ---- G0: X (fp16) + W1 (fp16) ----
    {
        const float4* xsrc = (const float4*)(g_Xh + ((size_t)m * B_ + r0) * IN_);
#pragma unroll
        for (int i = 0; i < 2; ++i) {          // 512 x 16B
            int idx = t + i * NTHR;
            int row = idx >> 3, c = idx & 7;
            cpa16(sb + SM_X + row * 128 + ((c ^ (row & 7)) << 4), xsrc + idx);
        }
        const float4* w1s = (const float4*)(g_W1Th + (size_t)m * H_ * IN_);
#pragma unroll
        for (int i = 0; i < 8; ++i) {          // 2048 x 16B
            int idx = t + i * NTHR;
            int row = idx >> 3, c = idx & 7;
            cpa16(sb + SM_W1 + row * 128 + ((c ^ (row & 7)) << 4), w1s + idx);
        }
    }
    CP_COMMIT();
    // ---- G1: W2 chunk 0 (k 0..63) -> ring slot 0 ----
#pragma unroll
    for (int i = 0; i < 8; ++i) {
        int idx = t + i * NTHR;
        int n = idx >> 3, c = idx & 7;
        cpa16(sb + SM_RING + n * 128 + ((c ^ (n & 7)) << 4),
              (const float4*)(w2m + (size_t)n * H_) + c);
    }
    CP_COMMIT();

    float acc[2][8][4];
#pragma unroll
    for (int mt = 0; mt < 2; ++mt)
#pragma unroll
        for (int nt = 0; nt < 8; ++nt)
#pragma unroll
            for (int j = 0; j < 4; ++j) acc[mt][nt][j] = 0.f;

    // ---- layer 1: K=64, 4 k16-steps (X, W1 resident) ----
    CP_WAIT(1);
    __syncthreads();
#pragma unroll
    for (int s = 0; s < 4; ++s)
        kstep(sb + SM_X, sb + SM_W1, s, m0, n0, lane, acc);

    // ---- epilogue 1: h1 = fp16(relu(acc + b1)) -> SM_H1 ----
#pragma unroll
    for (int nt = 0; nt < 8; ++nt) {
        int col = n0 + nt * 8 + 2 * tg;
        float2 bb = __ldg((const float2*)(b1g + m * H_ + col));
        int kseg = col >> 6;
        int ch   = (col & 63) >> 3;
        int boff = (col & 7) * 2;
#pragma unroll
        for (int mt = 0; mt < 2; ++mt) {
            float* c = acc[mt][nt];
#pragma unroll
            for (int h = 0; h < 2; ++h) {
                int row = m0 + mt * 16 + g + h * 8;
                __half2 v = __floats2half2_rn(fmaxf(c[2 * h]     + bb.x, 0.f),
                                              fmaxf(c[2 * h + 1] + bb.y, 0.f));
                *(__half2*)(smem + SM_H1 + kseg * 8192 + row * 128 +
                            ((ch ^ (row & 7)) << 4) + boff) = v;
            }
        }
    }
#pragma unroll
    for (int mt = 0; mt < 2; ++mt)
#pragma unroll
        for (int nt = 0; nt < 8; ++nt)
#pragma unroll
            for (int j = 0; j < 4; ++j) acc[mt][nt][j] = 0.f;
    __syncthreads();   // h1 visible; W1 region + X now dead

    // ---- G2: W2 chunk 1 -> slot 1 (overlays W1) ----
#pragma unroll
    for (int i = 0; i < 8; ++i) {
        int idx = t + i * NTHR;
        int n = idx >> 3, c = idx & 7;
        cpa16(sb + SM_W1 + n * 128 + ((c ^ (n & 7)) << 4),
              (const float4*)(w2m + (size_t)n * H_) + 8 + c);
    }
    CP_COMMIT();

    // ---- layer 2: K=256 = 4 chunks of 64, 2-slot ring ----
#pragma unroll
    for (int kc = 0; kc < 4; ++kc) {
        if (kc == 0) { CP_WAIT(1); } else { CP_WAIT(0); }
        __syncthreads();   // chunk kc visible; all warps done with kc-1 -> its slot free
        if (kc >= 1 && kc <= 2) {
            const int pc = kc + 1;    // prefetch chunk kc+1 into slot (pc&1)
            unsigned slot = (pc & 1) ? SM_W1 : SM_RING;
#pragma unroll
            for (int i = 0; i < 8; ++i) {
                int idx = t + i * NTHR;
                int n = idx >> 3, c = idx & 7;
                cpa16(sb + slot + n * 128 + ((c ^ (n & 7)) << 4),
                      (const float4*)(w2m + (size_t)n * H_) + pc * 8 + c);
            }
            CP_COMMIT();
        }
        unsigned Aseg = sb + SM_H1 + kc * 8192;
        unsigned Wseg = sb + ((kc & 1) ? SM_W1 : SM_RING);
#pragma unroll
        for (int s = 0; s < 4; ++s)
            kstep(Aseg, Wseg, s, m0, n0, lane, acc);
    }

    // ---- epilogue 2: out = relu(acc + b2) . w3 + b3 ----
    {
        float part[2][2] = {{0.f, 0.f}, {0.f, 0.f}};
#pragma unroll
        for (int nt = 0; nt < 8; ++nt) {
            int col = n0 + nt * 8 + 2 * tg;
            float2 bb = __ldg((const float2*)(b2g + m * H_ + col));
            float2 ww = __ldg((const float2*)(w3g + m * H_ + col));
#pragma unroll
            for (int mt = 0; mt < 2; ++mt) {
                float* c = acc[mt][nt];
                part[mt][0] = fmaf(fmaxf(c[0] + bb.x, 0.f), ww.x, part[mt][0]);
                part[mt][0] = fmaf(fmaxf(c[1] + bb.y, 0.f), ww.y, part[mt][0]);
                part[mt][1] = fmaf(fmaxf(c[2] + bb.x, 0.f), ww.x, part[mt][1]);
                part[mt][1] = fmaf(fmaxf(c[3] + bb.y, 0.f), ww.y, part[mt][1]);
            }
        }
#pragma unroll
        for (int sfl = 1; sfl < 4; sfl <<= 1)
#pragma unroll
            for (int mt = 0; mt < 2; ++mt) {
                part[mt][0] += __shfl_xor_sync(0xffffffffu, part[mt][0], sfl);
                part[mt][1] += __shfl_xor_sync(0xffffffffu, part[mt][1], sfl);
            }
        float* red = (float*)(smem + SM_RED);   // overlays dead X region
        __syncthreads();   // everyone done with layer-2 reads before X-alias write
        if (tg == 0) {
#pragma unroll
            for (int mt = 0; mt < 2; ++mt) {
                red[(m0 + mt * 16 + g) * 4     + (wid & 3)] = part[mt][0];
                red[(m0 + mt * 16 + g + 8) * 4 + (wid & 3)] = part[mt][1];
            }
        }
        __syncthreads();
        if (t < RT) {
            const float* r = red + t * 4;
            float s = (r[0] + r[1]) + (r[2] + r[3]);
            out[(size_t)m * B_ + r0 + t] = s + __ldg(b3g + m);
        }
    }
}

// ---------------- launcher ----------------
extern "C" void kernel_launch(void* const* d_in, const int* in_sizes, int n_in,
                              void* d_out, int out_size)
{
    const float* xs = (const float*)d_in[0];
    const float* W1 = (const float*)d_in[1];
    const float* b1 = (const float*)d_in[2];
    const float* W2 = (const float*)d_in[3];
    const float* b2 = (const float*)d_in[4];
    const float* W3 = (const float*)d_in[5];
    const float* b3 = (const float*)d_in[6];
    float* out = (float*)d_out;

    void* p1 = nullptr; void* p2 = nullptr; void* px = nullptr;
    cudaGetSymbolAddress(&p1, g_W1Th);
    cudaGetSymbolAddress(&p2, g_W2Th);
    cudaGetSymbolAddress(&px, g_Xh);

    dim3 tb(32, 8);
    transpose_cvt_all<<<dim3(H_ / 32, 10, M_), tb>>>(W1, W2, (__half*)p1, (__half*)p2);

    const int n4 = M_ * B_ * IN_ / 4;   // 4,194,304 float4s
    convert_x<<<(n4 + 1023) / 1024, 1024>>>((const float4*)xs, (uint2*)px, n4);

    cudaFuncSetAttribute(mlp_mma_f16,
                         cudaFuncAttributeMaxDynamicSharedMemorySize, SM_TOT);
    dim3 grid(B_ / RT, M_);   // 64 x 64 = 4096 CTAs, 2 per SM
    mlp_mma_f16<<<grid, NTHR, SM_TOT>>>(b1, b2, W3, b3, out);
}

// round 11
// speedup vs baseline: 3.1791x; 1.6233x over previous
#include <cuda_runtime.h>
#include <cuda_fp16.h>

// ---------------- problem constants ----------------
#define M_   64
#define IN_  64
#define H_   256
#define B_   4096
#define RT   64           // batch rows per CTA
#define NTHR 256          // 8 warps: grid 2m x 4n, warp tile 32x64

// ---------------- fp16 scratch (K-major weights) ----------------
__device__ __align__(16) __half g_W1Th[M_ * H_ * IN_];   // [m][n=256][k=64]   2 MB
__device__ __align__(16) __half g_W2Th[M_ * H_ * H_];    // [m][n=256][k=256]  8 MB

// ---------------- smem byte offsets (fp16 rows: 128B = 64 halves) ----------------
// swizzle: 16B chunk c of row r -> c ^ (r & 7)
#define SM_X    0          // X [64][128B] = 8192       (dead after layer 1 -> red)
#define SM_W1   8192       // W1 [256][128B] = 32768    (H1 overlays after layer 1)
#define SM_H1   8192       // h1: 4 ksegs x [64][128B] = 32768 (== SM_W1)
#define SM_RING0 40960     // W2 ring slot 0: 32768
#define SM_RING1 73728     // W2 ring slot 1: 32768
#define SM_TOT  106496     // x2 CTAs = 212992 <= carveout
#define SM_RED  SM_X       // red[64][4] floats overlays X

// ---------------- PTX helpers ----------------
__device__ __forceinline__ unsigned smem_u32(const void* p) {
    unsigned a;
    asm("{ .reg .u64 t; cvta.to.shared.u64 t, %1; cvt.u32.u64 %0, t; }" : "=r"(a) : "l"(p));
    return a;
}
__device__ __forceinline__ void cpa16(unsigned dst, const void* src) {
    asm volatile("cp.async.cg.shared.global [%0], [%1], 16;" :: "r"(dst), "l"(src));
}
#define CP_COMMIT()  asm volatile("cp.async.commit_group;" ::: "memory")
#define CP_WAIT(N)   asm volatile("cp.async.wait_group %0;" :: "n"(N) : "memory")

__device__ __forceinline__ void ldsm4(unsigned addr, unsigned r[4]) {
    asm volatile("ldmatrix.sync.aligned.m8n8.x4.shared.b16 {%0,%1,%2,%3}, [%4];"
        : "=r"(r[0]), "=r"(r[1]), "=r"(r[2]), "=r"(r[3]) : "r"(addr));
}
// fp16 m16n8k16, fp32 accumulate
__device__ __forceinline__ void mma16(float c[4], const unsigned a[4],
                                      unsigned b0, unsigned b1) {
    asm volatile("mma.sync.aligned.m16n8k16.row.col.f32.f16.f16.f32 "
        "{%0,%1,%2,%3},{%4,%5,%6,%7},{%8,%9},{%0,%1,%2,%3};"
        : "+f"(c[0]), "+f"(c[1]), "+f"(c[2]), "+f"(c[3])
        : "r"(a[0]), "r"(a[1]), "r"(a[2]), "r"(a[3]), "r"(b0), "r"(b1));
}

// one K=16 step, warp tile 32x64: A rows [m0..m0+32), W rows [n0..n0+64)
__device__ __forceinline__ void kstep(unsigned Aseg, unsigned Wseg, int s,
                                      int m0, int n0, int lane,
                                      float acc[2][8][4])
{
    const int rin = lane & 7, sub = lane >> 3;
    unsigned a[2][4], b[4][4];
    {
        int ch   = 2 * s + (sub >> 1);
        int roff = rin + (sub & 1) * 8;
#pragma unroll
        for (int mt = 0; mt < 2; ++mt) {
            int row = m0 + mt * 16 + roff;
            ldsm4(Aseg + row * 128 + ((ch ^ (row & 7)) << 4), a[mt]);
        }
    }
    {
        int ch   = 2 * s + (sub & 1);
        int roff = rin + (sub >> 1) * 8;
#pragma unroll
        for (int p = 0; p < 4; ++p) {
            int row = n0 + p * 16 + roff;
            ldsm4(Wseg + row * 128 + ((ch ^ (row & 7)) << 4), b[p]);
        }
    }
#pragma unroll
    for (int mt = 0; mt < 2; ++mt)
#pragma unroll
        for (int p = 0; p < 4; ++p) {
            mma16(acc[mt][2 * p],     a[mt], b[p][0], b[p][1]);
            mma16(acc[mt][2 * p + 1], a[mt], b[p][2], b[p][3]);
        }
}

// ---------------- prep: transpose weights to K-major fp16 (half2 stores) ----
// blockIdx.y == 0 -> W1 (K=64, one 64-k tile); 1..4 -> W2 k-tiles
__global__ void transpose_cvt_all(const float* __restrict__ W1,
                                  const float* __restrict__ W2,
                                  __half* __restrict__ W1T,
                                  __half* __restrict__ W2T)
{
    __shared__ float tile[64][33];
    const int m = blockIdx.z;
    const float* in;
    __half* out;
    int K, kt;
    if (blockIdx.y == 0) { in = W1; out = W1T; K = IN_; kt = 0; }
    else                 { in = W2; out = W2T; K = H_;  kt = blockIdx.y - 1; }
    in  += (size_t)m * K * H_;
    out += (size_t)m * K * H_;
    const int n0 = blockIdx.x * 32, k0 = kt * 64;
    const int tx = threadIdx.x, ty = threadIdx.y;   // 32 x 8
#pragma unroll
    for (int j = ty; j < 64; j += 8)
        tile[j][tx] = in[(size_t)(k0 + j) * H_ + n0 + tx];
    __syncthreads();
#pragma unroll
    for (int j = ty; j < 32; j += 8) {
        __half2 v = __floats2half2_rn(tile[2 * tx][j], tile[2 * tx + 1][j]);
        *(__half2*)(out + (size_t)(n0 + j) * K + k0 + 2 * tx) = v;
    }
}

// ---------------- fused MLP kernel (fp16 MMA, 2 CTAs/SM) ----------------
__global__ __launch_bounds__(NTHR, 2)
void mlp_mma_f16(const float* __restrict__ xs,
                 const float* __restrict__ b1g,
                 const float* __restrict__ b2g,
                 const float* __restrict__ w3g,
                 const float* __restrict__ b3g,
                 float* __restrict__ out)
{
    extern __shared__ char smem[];
    const unsigned sb = smem_u32(smem);
    const int t    = threadIdx.x;
    const int lane = t & 31;
    const int wid  = t >> 5;
    const int m    = blockIdx.y;
    const int r0   = blockIdx.x * RT;
    const int m0   = (wid >> 2) * 32;     // warp row base (0 / 32)
    const int n0   = (wid & 3) * 64;      // warp col base (0/64/128/192)
    const int g    = lane >> 2;
    const int tg   = lane & 3;

    const __half* w2m = g_W2Th + (size_t)m * H_ * H_;

    // ---- G0: W1 via cp.async ----
    {
        const float4* w1s = (const float4*)(g_W1Th + (size_t)m * H_ * IN_);
#pragma unroll
        for (int i = 0; i < 8; ++i) {          // 2048 x 16B
            int idx = t + i * NTHR;
            int row = idx >> 3, c = idx & 7;
            cpa16(sb + SM_W1 + row * 128 + ((c ^ (row & 7)) << 4), w1s + idx);
        }
    }
    CP_COMMIT();
    // ---- G1, G2: W2 chunks 0,1 -> dedicated ring slots ----
#pragma unroll
    for (int kb = 0; kb < 2; ++kb) {
        unsigned slot = kb ? SM_RING1 : SM_RING0;
#pragma unroll
        for (int i = 0; i < 8; ++i) {
            int idx = t + i * NTHR;
            int n = idx >> 3, c = idx & 7;
            cpa16(sb + slot + n * 128 + ((c ^ (n & 7)) << 4),
                  (const float4*)(w2m + (size_t)n * H_) + kb * 8 + c);
        }
        CP_COMMIT();
    }

    // ---- X: load fp32, convert, store fp16 to SM_X ----
    {
        const float* xsrc = xs + ((size_t)m * B_ + r0) * IN_;
#pragma unroll
        for (int i = 0; i < 2; ++i) {
            int idx = t + i * NTHR;            // 512 chunks of 8 halves
            int row = idx >> 3, c = idx & 7;
            const float4* p = (const float4*)(xsrc + row * IN_ + c * 8);
            float4 v0 = __ldg(p), v1 = __ldg(p + 1);
            __half2 h0 = __floats2half2_rn(v0.x, v0.y);
            __half2 h1 = __floats2half2_rn(v0.z, v0.w);
            __half2 h2 = __floats2half2_rn(v1.x, v1.y);
            __half2 h3 = __floats2half2_rn(v1.z, v1.w);
            uint4 u;
            u.x = *(unsigned*)&h0; u.y = *(unsigned*)&h1;
            u.z = *(unsigned*)&h2; u.w = *(unsigned*)&h3;
            *(uint4*)(smem + SM_X + row * 128 + ((c ^ (row & 7)) << 4)) = u;
        }
    }

    float acc[2][8][4];
#pragma unroll
    for (int mt = 0; mt < 2; ++mt)
#pragma unroll
        for (int nt = 0; nt < 8; ++nt)
#pragma unroll
            for (int j = 0; j < 4; ++j) acc[mt][nt][j] = 0.f;

    // ---- layer 1: K=64, 4 k16-steps ----
    CP_WAIT(2);        // G0 (W1) done; chunks 0,1 still streaming
    __syncthreads();   // X STS visible
#pragma unroll
    for (int s = 0; s < 4; ++s)
        kstep(sb + SM_X, sb + SM_W1, s, m0, n0, lane, acc);
    __syncthreads();   // all warps done reading W1 before H1 overlays it

    // ---- epilogue 1: h1 = fp16(relu(acc + b1)) -> SM_H1 (over W1) ----
#pragma unroll
    for (int nt = 0; nt < 8; ++nt) {
        int col = n0 + nt * 8 + 2 * tg;
        float2 bb = __ldg((const float2*)(b1g + m * H_ + col));
        int kseg = col >> 6;
        int ch   = (col & 63) >> 3;
        int boff = (col & 7) * 2;
#pragma unroll
        for (int mt = 0; mt < 2; ++mt) {
            float* c = acc[mt][nt];
#pragma unroll
            for (int h = 0; h < 2; ++h) {
                int row = m0 + mt * 16 + g + h * 8;
                __half2 v = __floats2half2_rn(fmaxf(c[2 * h]     + bb.x, 0.f),
                                              fmaxf(c[2 * h + 1] + bb.y, 0.f));
                *(__half2*)(smem + SM_H1 + kseg * 8192 + row * 128 +
                            ((ch ^ (row & 7)) << 4) + boff) = v;
            }
        }
    }
#pragma unroll
    for (int mt = 0; mt < 2; ++mt)
#pragma unroll
        for (int nt = 0; nt < 8; ++nt)
#pragma unroll
            for (int j = 0; j < 4; ++j) acc[mt][nt][j] = 0.f;
    __syncthreads();   // h1 visible

    // ---- layer 2: K=256 = 4 chunks of 64, 2-slot ring ----
#pragma unroll
    for (int kc = 0; kc < 4; ++kc) {
        if (kc == 0) { CP_WAIT(1); } else { CP_WAIT(0); }
        __syncthreads();   // chunk kc visible; all warps done with kc-1
        if (kc == 1 || kc == 2) {
            const int pc = kc + 1;    // prefetch chunk kc+1 into freed slot
            unsigned slot = (pc & 1) ? SM_RING1 : SM_RING0;
#pragma unroll
            for (int i = 0; i < 8; ++i) {
                int idx = t + i * NTHR;
                int n = idx >> 3, c = idx & 7;
                cpa16(sb + slot + n * 128 + ((c ^ (n & 7)) << 4),
                      (const float4*)(w2m + (size_t)n * H_) + pc * 8 + c);
            }
            CP_COMMIT();
        }
        unsigned Aseg = sb + SM_H1 + kc * 8192;
        unsigned Wseg = sb + ((kc & 1) ? SM_RING1 : SM_RING0);
#pragma unroll
        for (int s = 0; s < 4; ++s)
            kstep(Aseg, Wseg, s, m0, n0, lane, acc);
    }

    // ---- epilogue 2: out = relu(acc + b2) . w3 + b3 ----
    {
        float part[2][2] = {{0.f, 0.f}, {0.f, 0.f}};
#pragma unroll
        for (int nt = 0; nt < 8; ++nt) {
            int col = n0 + nt * 8 + 2 * tg;
            float2 bb = __ldg((const float2*)(b2g + m * H_ + col));
            float2 ww = __ldg((const float2*)(w3g + m * H_ + col));
#pragma unroll
            for (int mt = 0; mt < 2; ++mt) {
                float* c = acc[mt][nt];
                part[mt][0] = fmaf(fmaxf(c[0] + bb.x, 0.f), ww.x, part[mt][0]);
                part[mt][0] = fmaf(fmaxf(c[1] + bb.y, 0.f), ww.y, part[mt][0]);
                part[mt][1] = fmaf(fmaxf(c[2] + bb.x, 0.f), ww.x, part[mt][1]);
                part[mt][1] = fmaf(fmaxf(c[3] + bb.y, 0.f), ww.y, part[mt][1]);
            }
        }
#pragma unroll
        for (int sfl = 1; sfl < 4; sfl <<= 1)
#pragma unroll
            for (int mt = 0; mt < 2; ++mt) {
                part[mt][0] += __shfl_xor_sync(0xffffffffu, part[mt][0], sfl);
                part[mt][1] += __shfl_xor_sync(0xffffffffu, part[mt][1], sfl);
            }
        float* red = (float*)(smem + SM_RED);   // overlays dead X region
        __syncthreads();   // everyone done with layer-2 reads before X-alias write
        if (tg == 0) {
#pragma unroll
            for (int mt = 0; mt < 2; ++mt) {
                red[(m0 + mt * 16 + g) * 4     + (wid & 3)] = part[mt][0];
                red[(m0 + mt * 16 + g + 8) * 4 + (wid & 3)] = part[mt][1];
            }
        }
        __syncthreads();
        if (t < RT) {
            const float* r = red + t * 4;
            float s = (r[0] + r[1]) + (r[2] + r[3]);
            out[(size_t)m * B_ + r0 + t] = s + __ldg(b3g + m);
        }
    }
}

// ---------------- launcher ----------------
extern "C" void kernel_launch(void* const* d_in, const int* in_sizes, int n_in,
                              void* d_out, int out_size)
{
    const float* xs = (const float*)d_in[0];
    const float* W1 = (const float*)d_in[1];
    const float* b1 = (const float*)d_in[2];
    const float* W2 = (const float*)d_in[3];
    const float* b2 = (const float*)d_in[4];
    const float* W3 = (const float*)d_in[5];
    const float* b3 = (const float*)d_in[6];
    float* out = (float*)d_out;

    void* p1 = nullptr; void* p2 = nullptr;
    cudaGetSymbolAddress(&p1, g_W1Th);
    cudaGetSymbolAddress(&p2, g_W2Th);

    dim3 tb(32, 8);
    transpose_cvt_all<<<dim3(H_ / 32, 5, M_), tb>>>(W1, W2, (__half*)p1, (__half*)p2);

    cudaFuncSetAttribute(mlp_mma_f16,
                         cudaFuncAttributeMaxDynamicSharedMemorySize, SM_TOT);
    dim3 grid(B_ / RT, M_);   // 64 x 64 = 4096 CTAs, 2 per SM
    mlp_mma_f16<<<grid, NTHR, SM_TOT>>>(xs, b1, b2, W3, b3, out);
}

// round 15
// speedup vs baseline: 3.3157x; 1.0430x over previous
#include <cuda_runtime.h>
#include <cuda_fp16.h>

// ---------------- problem constants ----------------
#define M_   64
#define IN_  64
#define H_   256
#define B_   4096
#define RT   64           // batch rows per CTA
#define NTHR 256          // 8 warps: grid 2m x 4n, warp tile 32x64

// ---------------- fp16 scratch (K-major weights) ----------------
__device__ __align__(16) __half g_W1Th[M_ * H_ * IN_];   // [m][n=256][k=64]   2 MB
__device__ __align__(16) __half g_W2Th[M_ * H_ * H_];    // [m][n=256][k=256]  8 MB

// ---------------- smem byte offsets (fp16 rows: 128B = 64 halves) ----------------
// swizzle: 16B chunk c of row r -> c ^ (r & 7)
#define SM_X    0          // X [64][128B] = 8192       (dead after layer 1 -> red)
#define SM_W1   8192       // W1 [256][128B] = 32768    (H1 overlays after layer 1)
#define SM_H1   8192       // h1: 4 ksegs x [64][128B] = 32768 (== SM_W1)
#define SM_RING0 40960     // W2 ring slot 0: 32768
#define SM_RING1 73728     // W2 ring slot 1: 32768
#define SM_TOT  106496     // x2 CTAs = 212992 <= carveout
#define SM_RED  SM_X       // red[64][4] floats overlays X

// ---------------- PTX helpers ----------------
__device__ __forceinline__ unsigned smem_u32(const void* p) {
    unsigned a;
    asm("{ .reg .u64 t; cvta.to.shared.u64 t, %1; cvt.u32.u64 %0, t; }" : "=r"(a) : "l"(p));
    return a;
}
__device__ __forceinline__ void cpa16(unsigned dst, const void* src) {
    asm volatile("cp.async.cg.shared.global [%0], [%1], 16;" :: "r"(dst), "l"(src));
}
#define CP_COMMIT()  asm volatile("cp.async.commit_group;" ::: "memory")
#define CP_WAIT(N)   asm volatile("cp.async.wait_group %0;" :: "n"(N) : "memory")

__device__ __forceinline__ void ldsm4(unsigned addr, unsigned r[4]) {
    asm volatile("ldmatrix.sync.aligned.m8n8.x4.shared.b16 {%0,%1,%2,%3}, [%4];"
        : "=r"(r[0]), "=r"(r[1]), "=r"(r[2]), "=r"(r[3]) : "r"(addr));
}
// fp16 m16n8k16, fp32 accumulate
__device__ __forceinline__ void mma16(float c[4], const unsigned a[4],
                                      unsigned b0, unsigned b1) {
    asm volatile("mma.sync.aligned.m16n8k16.row.col.f32.f16.f16.f32 "
        "{%0,%1,%2,%3},{%4,%5,%6,%7},{%8,%9},{%0,%1,%2,%3};"
        : "+f"(c[0]), "+f"(c[1]), "+f"(c[2]), "+f"(c[3])
        : "r"(a[0]), "r"(a[1]), "r"(a[2]), "r"(a[3]), "r"(b0), "r"(b1));
}

// one K=16 step, warp tile 32x64, precomputed s=0 byte offsets.
// chunk index ch = 2s + bit (bit = per-thread LSB), swizzled: (ch ^ (row&7))<<4.
// Since bit is the LSB and 2s only sets higher bits, 2s+bit == (2s | bit), so
// addr(s) = [row*128 + ((bit ^ (row&7))<<4)] ^ (s<<5)  — a single XOR per step.
__device__ __forceinline__ void kstep2(unsigned Aseg, unsigned Wseg, unsigned sxor,
                                       const unsigned aoff0[2],
                                       const unsigned boff0[4],
                                       float acc[2][8][4])
{
    unsigned a[2][4], b[4][4];
#pragma unroll
    for (int mt = 0; mt < 2; ++mt)
        ldsm4(Aseg + (aoff0[mt] ^ sxor), a[mt]);
#pragma unroll
    for (int p = 0; p < 4; ++p)
        ldsm4(Wseg + (boff0[p] ^ sxor), b[p]);
#pragma unroll
    for (int mt = 0; mt < 2; ++mt)
#pragma unroll
        for (int p = 0; p < 4; ++p) {
            mma16(acc[mt][2 * p],     a[mt], b[p][0], b[p][1]);
            mma16(acc[mt][2 * p + 1], a[mt], b[p][2], b[p][3]);
        }
}

// ---------------- prep: transpose weights to K-major fp16 (uint4 stores) ----
// 64n x 64k tile per block, 256 threads.
// blockIdx.y: 0 -> W1 (K=64); 1..4 -> W2 ktile
__global__ void transpose_cvt_all(const float* __restrict__ W1,
                                  const float* __restrict__ W2,
                                  __half* __restrict__ W1T,
                                  __half* __restrict__ W2T)
{
    __shared__ float tile[64][68];
    const int m = blockIdx.z;
    const float* in;
    __half* out;
    int K, kt;
    if (blockIdx.y == 0) { in = W1; out = W1T; K = IN_; kt = 0; }
    else                 { in = W2; out = W2T; K = H_;  kt = blockIdx.y - 1; }
    in  += (size_t)m * K * H_;
    out += (size_t)m * K * H_;
    const int n0 = blockIdx.x * 64, k0 = kt * 64;
    const int t = threadIdx.x;
    // load 64 k-rows x 64 n-cols as float4 (16 float4/row, 4 rows per pass)
    {
        const int rr = t >> 4, cc = t & 15;
#pragma unroll
        for (int j = 0; j < 4; ++j) {
            int k = rr + j * 16;
            float4 v = *(const float4*)(in + (size_t)(k0 + k) * H_ + n0 + cc * 4);
            tile[k][cc * 4 + 0] = v.x;
            tile[k][cc * 4 + 1] = v.y;
            tile[k][cc * 4 + 2] = v.z;
            tile[k][cc * 4 + 3] = v.w;
        }
    }
    __syncthreads();
    // store 64 n-rows x 64 k-halves: 8 uint4 per n-row, 2 per thread
    {
        const int nr = t >> 2, cc = t & 3;
#pragma unroll
        for (int j = 0; j < 2; ++j) {
            int c8 = cc * 2 + j;               // 8-half group 0..7
            __half2 h[4];
#pragma unroll
            for (int q = 0; q < 4; ++q)
                h[q] = __floats2half2_rn(tile[c8 * 8 + 2 * q][nr],
                                         tile[c8 * 8 + 2 * q + 1][nr]);
            uint4 u;
            u.x = *(unsigned*)&h[0]; u.y = *(unsigned*)&h[1];
            u.z = *(unsigned*)&h[2]; u.w = *(unsigned*)&h[3];
            *(uint4*)(out + (size_t)(n0 + nr) * K + k0 + c8 * 8) = u;
        }
    }
}

// ---------------- fused MLP kernel (fp16 MMA, 2 CTAs/SM) ----------------
__global__ __launch_bounds__(NTHR, 2)
void mlp_mma_f16(const float* __restrict__ xs,
                 const float* __restrict__ b1g,
                 const float* __restrict__ b2g,
                 const float* __restrict__ w3g,
                 const float* __restrict__ b3g,
                 float* __restrict__ out)
{
    extern __shared__ char smem[];
    const unsigned sb = smem_u32(smem);
    const int t    = threadIdx.x;
    const int lane = t & 31;
    const int wid  = t >> 5;
    const int m    = blockIdx.y;
    const int r0   = blockIdx.x * RT;
    const int m0   = (wid >> 2) * 32;     // warp row base (0 / 32)
    const int n0   = (wid & 3) * 64;      // warp col base (0/64/128/192)
    const int g    = lane >> 2;
    const int tg   = lane & 3;

    // precomputed ldmatrix s=0 byte offsets
    const int rin = lane & 7, sub = lane >> 3;
    unsigned aoff0[2], boff0[4];
    {
        int bit  = sub >> 1;                 // A chunk LSB
        int roff = rin + (sub & 1) * 8;
#pragma unroll
        for (int mt = 0; mt < 2; ++mt) {
            int row = m0 + mt * 16 + roff;
            aoff0[mt] = (unsigned)(row * 128) + (((unsigned)(bit ^ (row & 7))) << 4);
        }
        bit  = sub & 1;                      // B chunk LSB
        roff = rin + (sub >> 1) * 8;
#pragma unroll
        for (int p = 0; p < 4; ++p) {
            int row = n0 + p * 16 + roff;
            boff0[p] = (unsigned)(row * 128) + (((unsigned)(bit ^ (row & 7))) << 4);
        }
    }

    const __half* w2m = g_W2Th + (size_t)m * H_ * H_;

    // ---- G0: W1 via cp.async ----
    {
        const float4* w1s = (const float4*)(g_W1Th + (size_t)m * H_ * IN_);
#pragma unroll
        for (int i = 0; i < 8; ++i) {          // 2048 x 16B
            int idx = t + i * NTHR;
            int row = idx >> 3, c = idx & 7;
            cpa16(sb + SM_W1 + row * 128 + ((c ^ (row & 7)) << 4), w1s + idx);
        }
    }
    CP_COMMIT();
    // ---- G1, G2: W2 chunks 0,1 -> dedicated ring slots ----
#pragma unroll
    for (int kb = 0; kb < 2; ++kb) {
        unsigned slot = kb ? SM_RING1 : SM_RING0;
#pragma unroll
        for (int i = 0; i < 8; ++i) {
            int idx = t + i * NTHR;
            int n = idx >> 3, c = idx & 7;
            cpa16(sb + slot + n * 128 + ((c ^ (n & 7)) << 4),
                  (const float4*)(w2m + (size_t)n * H_) + kb * 8 + c);
        }
        CP_COMMIT();
    }

    // ---- X: load fp32, convert, store fp16 to SM_X ----
    {
        const float* xsrc = xs + ((size_t)m * B_ + r0) * IN_;
#pragma unroll
        for (int i = 0; i < 2; ++i) {
            int idx = t + i * NTHR;            // 512 chunks of 8 halves
            int row = idx >> 3, c = idx & 7;
            const float4* p = (const float4*)(xsrc + row * IN_ + c * 8);
            float4 v0 = __ldg(p), v1 = __ldg(p + 1);
            __half2 h0 = __floats2half2_rn(v0.x, v0.y);
            __half2 h1 = __floats2half2_rn(v0.z, v0.w);
            __half2 h2 = __floats2half2_rn(v1.x, v1.y);
            __half2 h3 = __floats2half2_rn(v1.z, v1.w);
            uint4 u;
            u.x = *(unsigned*)&h0; u.y = *(unsigned*)&h1;
            u.z = *(unsigned*)&h2; u.w = *(unsigned*)&h3;
            *(uint4*)(smem + SM_X + row * 128 + ((c ^ (row & 7)) << 4)) = u;
        }
    }

    float acc[2][8][4];
#pragma unroll
    for (int mt = 0; mt < 2; ++mt)
#pragma unroll
        for (int nt = 0; nt < 8; ++nt)
#pragma unroll
            for (int j = 0; j < 4; ++j) acc[mt][nt][j] = 0.f;

    // ---- layer 1: K=64, 4 k16-steps ----
    CP_WAIT(2);        // G0 (W1) done; chunks 0,1 still streaming
    __syncthreads();   // X STS visible
#pragma unroll
    for (int s = 0; s < 4; ++s)
        kstep2(sb + SM_X, sb + SM_W1, (unsigned)(s << 5), aoff0, boff0, acc);
    __syncthreads();   // all warps done reading W1 before H1 overlays it

    // ---- epilogue 1: h1 = fp16(relu(acc + b1)) -> SM_H1 (over W1) ----
#pragma unroll
    for (int nt = 0; nt < 8; ++nt) {
        int col = n0 + nt * 8 + 2 * tg;
        float2 bb = __ldg((const float2*)(b1g + m * H_ + col));
        int kseg = col >> 6;
        int ch   = (col & 63) >> 3;
        int boff = (col & 7) * 2;
#pragma unroll
        for (int mt = 0; mt < 2; ++mt) {
            float* c = acc[mt][nt];
#pragma unroll
            for (int h = 0; h < 2; ++h) {
                int row = m0 + mt * 16 + g + h * 8;
                __half2 v = __floats2half2_rn(fmaxf(c[2 * h]     + bb.x, 0.f),
                                              fmaxf(c[2 * h + 1] + bb.y, 0.f));
                *(__half2*)(smem + SM_H1 + kseg * 8192 + row * 128 +
                            ((ch ^ (row & 7)) << 4) + boff) = v;
            }
        }
    }
#pragma unroll
    for (int mt = 0; mt < 2; ++mt)
#pragma unroll
        for (int nt = 0; nt < 8; ++nt)
#pragma unroll
            for (int j = 0; j < 4; ++j) acc[mt][nt][j] = 0.f;
    __syncthreads();   // h1 visible

    // ---- layer 2: K=256 = 4 chunks of 64, 2-slot ring ----
#pragma unroll
    for (int kc = 0; kc < 4; ++kc) {
        if (kc == 0) { CP_WAIT(1); } else { CP_WAIT(0); }
        __syncthreads();   // chunk kc visible; all warps done with kc-1
        if (kc == 1 || kc == 2) {
            const int pc = kc + 1;    // prefetch chunk kc+1 into freed slot
            unsigned slot = (pc & 1) ? SM_RING1 : SM_RING0;
#pragma unroll
            for (int i = 0; i < 8; ++i) {
                int idx = t + i * NTHR;
                int n = idx >> 3, c = idx & 7;
                cpa16(sb + slot + n * 128 + ((c ^ (n & 7)) << 4),
                      (const float4*)(w2m + (size_t)n * H_) + pc * 8 + c);
            }
            CP_COMMIT();
        }
        unsigned Aseg = sb + SM_H1 + kc * 8192;
        unsigned Wseg = sb + ((kc & 1) ? SM_RING1 : SM_RING0);
#pragma unroll
        for (int s = 0; s < 4; ++s)
            kstep2(Aseg, Wseg, (unsigned)(s << 5), aoff0, boff0, acc);
    }

    // ---- epilogue 2: out = relu(acc + b2) . w3 + b3 ----
    {
        float part[2][2] = {{0.f, 0.f}, {0.f, 0.f}};
#pragma unroll
        for (int nt = 0; nt < 8; ++nt) {
            int col = n0 + nt * 8 + 2 * tg;
            float2 bb = __ldg((const float2*)(b2g + m * H_ + col));
            float2 ww = __ldg((const float2*)(w3g + m * H_ + col));
#pragma unroll
            for (int mt = 0; mt < 2; ++mt) {
                float* c = acc[mt][nt];
                part[mt][0] = fmaf(fmaxf(c[0] + bb.x, 0.f), ww.x, part[mt][0]);
                part[mt][0] = fmaf(fmaxf(c[1] + bb.y, 0.f), ww.y, part[mt][0]);
                part[mt][1] = fmaf(fmaxf(c[2] + bb.x, 0.f), ww.x, part[mt][1]);
                part[mt][1] = fmaf(fmaxf(c[3] + bb.y, 0.f), ww.y, part[mt][1]);
            }
        }
#pragma unroll
        for (int sfl = 1; sfl < 4; sfl <<= 1)
#pragma unroll
            for (int mt = 0; mt < 2; ++mt) {
                part[mt][0] += __shfl_xor_sync(0xffffffffu, part[mt][0], sfl);
                part[mt][1] += __shfl_xor_sync(0xffffffffu, part[mt][1], sfl);
            }
        float* red = (float*)(smem + SM_RED);   // overlays dead X region
        __syncthreads();   // everyone done with layer-2 reads before X-alias write
        if (tg == 0) {
#pragma unroll
            for (int mt = 0; mt < 2; ++mt) {
                red[(m0 + mt * 16 + g) * 4     + (wid & 3)] = part[mt][0];
                red[(m0 + mt * 16 + g + 8) * 4 + (wid & 3)] = part[mt][1];
            }
        }
        __syncthreads();
        if (t < RT) {
            const float* r = red + t * 4;
            float s = (r[0] + r[1]) + (r[2] + r[3]);
            out[(size_t)m * B_ + r0 + t] = s + __ldg(b3g + m);
        }
    }
}

// ---------------- launcher ----------------
extern "C" void kernel_launch(void* const* d_in, const int* in_sizes, int n_in,
                              void* d_out, int out_size)
{
    const float* xs = (const float*)d_in[0];
    const float* W1 = (const float*)d_in[1];
    const float* b1 = (const float*)d_in[2];
    const float* W2 = (const float*)d_in[3];
    const float* b2 = (const float*)d_in[4];
    const float* W3 = (const float*)d_in[5];
    const float* b3 = (const float*)d_in[6];
    float* out = (float*)d_out;

    void* p1 = nullptr; void* p2 = nullptr;
    cudaGetSymbolAddress(&p1, g_W1Th);
    cudaGetSymbolAddress(&p2, g_W2Th);

    // grid: x = n-tiles of 64, y = 5 (W1 ktile + 4 W2 ktiles), z = models
    transpose_cvt_all<<<dim3(H_ / 64, 5, M_), 256>>>(W1, W2, (__half*)p1, (__half*)p2);

    cudaFuncSetAttribute(mlp_mma_f16,
                         cudaFuncAttributeMaxDynamicSharedMemorySize, SM_TOT);
    dim3 grid(B_ / RT, M_);   // 64 x 64 = 4096 CTAs, 2 per SM
    mlp_mma_f16<<<grid, NTHR, SM_TOT>>>(xs, b1, b2, W3, b3, out);
}

// round 17
// speedup vs baseline: 3.4894x; 1.0524x over previous
#include <cuda_runtime.h>
#include <cuda_fp16.h>

// ---------------- problem constants ----------------
#define M_   64
#define IN_  64
#define H_   256
#define B_   4096
#define RT   64           // batch rows per CTA
#define NTHR 256          // 8 warps: grid 2m x 4n, warp tile 32x64

// ---------------- fp16 scratch (K-major weights) ----------------
__device__ __align__(16) __half g_W1Th[M_ * H_ * IN_];   // [m][n=256][k=64]   2 MB
__device__ __align__(16) __half g_W2Th[M_ * H_ * H_];    // [m][n=256][k=256]  8 MB

// ---------------- smem byte offsets (fp16 rows: 128B = 64 halves) ----------------
// swizzle: 16B chunk c of row r -> c ^ (r & 7)
#define SM_X    0          // X [64][128B] = 8192       (dead after layer 1 -> red)
#define SM_W1   8192       // W1 [256][128B] = 32768    (H1 overlays after layer 1)
#define SM_H1   8192       // h1: 4 ksegs x [64][128B] = 32768 (== SM_W1)
#define SM_RING0 40960     // W2 ring slot 0: 32768
#define SM_RING1 73728     // W2 ring slot 1: 32768
#define SM_TOT  106496     // x2 CTAs = 212992 <= carveout
#define SM_RED  SM_X       // red[64][4] floats overlays X

// ---------------- PTX helpers ----------------
__device__ __forceinline__ unsigned smem_u32(const void* p) {
    unsigned a;
    asm("{ .reg .u64 t; cvta.to.shared.u64 t, %1; cvt.u32.u64 %0, t; }" : "=r"(a) : "l"(p));
    return a;
}
__device__ __forceinline__ void cpa16(unsigned dst, const void* src) {
    asm volatile("cp.async.cg.shared.global [%0], [%1], 16;" :: "r"(dst), "l"(src));
}
#define CP_COMMIT()  asm volatile("cp.async.commit_group;" ::: "memory")
#define CP_WAIT(N)   asm volatile("cp.async.wait_group %0;" :: "n"(N) : "memory")

__device__ __forceinline__ void ldsm4(unsigned addr, unsigned r[4]) {
    asm volatile("ldmatrix.sync.aligned.m8n8.x4.shared.b16 {%0,%1,%2,%3}, [%4];"
        : "=r"(r[0]), "=r"(r[1]), "=r"(r[2]), "=r"(r[3]) : "r"(addr));
}
// fp16 m16n8k16, fp32 accumulate
__device__ __forceinline__ void mma16(float c[4], const unsigned a[4],
                                      unsigned b0, unsigned b1) {
    asm volatile("mma.sync.aligned.m16n8k16.row.col.f32.f16.f16.f32 "
        "{%0,%1,%2,%3},{%4,%5,%6,%7},{%8,%9},{%0,%1,%2,%3};"
        : "+f"(c[0]), "+f"(c[1]), "+f"(c[2]), "+f"(c[3])
        : "r"(a[0]), "r"(a[1]), "r"(a[2]), "r"(a[3]), "r"(b0), "r"(b1));
}

// one K=16 step, warp tile 32x64, precomputed s=0 byte offsets.
// chunk index ch = 2s + bit (bit = per-thread LSB), swizzled: (ch ^ (row&7))<<4.
// Since bit is the LSB and 2s only sets higher bits, 2s+bit == (2s | bit), so
// addr(s) = [row*128 + ((bit ^ (row&7))<<4)] ^ (s<<5)  — a single XOR per step.
__device__ __forceinline__ void kstep2(unsigned Aseg, unsigned Wseg, unsigned sxor,
                                       const unsigned aoff0[2],
                                       const unsigned boff0[4],
                                       float acc[2][8][4])
{
    unsigned a[2][4], b[4][4];
#pragma unroll
    for (int mt = 0; mt < 2; ++mt)
        ldsm4(Aseg + (aoff0[mt] ^ sxor), a[mt]);
#pragma unroll
    for (int p = 0; p < 4; ++p)
        ldsm4(Wseg + (boff0[p] ^ sxor), b[p]);
#pragma unroll
    for (int mt = 0; mt < 2; ++mt)
#pragma unroll
        for (int p = 0; p < 4; ++p) {
            mma16(acc[mt][2 * p],     a[mt], b[p][0], b[p][1]);
            mma16(acc[mt][2 * p + 1], a[mt], b[p][2], b[p][3]);
        }
}

// ---------------- prep: transpose weights to K-major fp16 (uint4 stores) ----
// 64n x 64k tile per block, 256 threads.
// blockIdx.y: 0 -> W1 (K=64); 1..4 -> W2 ktile
__global__ void transpose_cvt_all(const float* __restrict__ W1,
                                  const float* __restrict__ W2,
                                  __half* __restrict__ W1T,
                                  __half* __restrict__ W2T)
{
    __shared__ float tile[64][68];
    const int m = blockIdx.z;
    const float* in;
    __half* out;
    int K, kt;
    if (blockIdx.y == 0) { in = W1; out = W1T; K = IN_; kt = 0; }
    else                 { in = W2; out = W2T; K = H_;  kt = blockIdx.y - 1; }
    in  += (size_t)m * K * H_;
    out += (size_t)m * K * H_;
    const int n0 = blockIdx.x * 64, k0 = kt * 64;
    const int t = threadIdx.x;
    // load 64 k-rows x 64 n-cols as float4 (16 float4/row, 4 rows per pass)
    {
        const int rr = t >> 4, cc = t & 15;
#pragma unroll
        for (int j = 0; j < 4; ++j) {
            int k = rr + j * 16;
            float4 v = *(const float4*)(in + (size_t)(k0 + k) * H_ + n0 + cc * 4);
            tile[k][cc * 4 + 0] = v.x;
            tile[k][cc * 4 + 1] = v.y;
            tile[k][cc * 4 + 2] = v.z;
            tile[k][cc * 4 + 3] = v.w;
        }
    }
    __syncthreads();
    // store 64 n-rows x 64 k-halves: 8 uint4 per n-row, 2 per thread
    {
        const int nr = t >> 2, cc = t & 3;
#pragma unroll
        for (int j = 0; j < 2; ++j) {
            int c8 = cc * 2 + j;               // 8-half group 0..7
            __half2 h[4];
#pragma unroll
            for (int q = 0; q < 4; ++q)
                h[q] = __floats2half2_rn(tile[c8 * 8 + 2 * q][nr],
                                         tile[c8 * 8 + 2 * q + 1][nr]);
            uint4 u;
            u.x = *(unsigned*)&h[0]; u.y = *(unsigned*)&h[1];
            u.z = *(unsigned*)&h[2]; u.w = *(unsigned*)&h[3];
            *(uint4*)(out + (size_t)(n0 + nr) * K + k0 + c8 * 8) = u;
        }
    }
}

// ---------------- fused MLP kernel (fp16 MMA, 2 CTAs/SM) ----------------
__global__ __launch_bounds__(NTHR, 2)
void mlp_mma_f16(const float* __restrict__ xs,
                 const float* __restrict__ b1g,
                 const float* __restrict__ b2g,
                 const float* __restrict__ w3g,
                 const float* __restrict__ b3g,
                 float* __restrict__ out)
{
    extern __shared__ char smem[];
    const unsigned sb = smem_u32(smem);
    const int t    = threadIdx.x;
    const int lane = t & 31;
    const int wid  = t >> 5;
    const int m    = blockIdx.y;
    const int r0   = blockIdx.x * RT;
    const int m0   = (wid >> 2) * 32;     // warp row base (0 / 32)
    const int n0   = (wid & 3) * 64;      // warp col base (0/64/128/192)
    const int g    = lane >> 2;
    const int tg   = lane & 3;

    // hoisted per-thread W2-prefetch addressing (invariant across iters/chunks)
    const int pn   = t >> 3;              // base n-row (0..31), advances +32/iter
    const int pc   = t & 7;               // 16B column, constant
    const unsigned pswz = (unsigned)((pc ^ (pn & 7)) << 4);  // (n&7) invariant
    const unsigned pdst0 = (unsigned)(pn * 128) + pswz;      // + i*4096 per iter
    const __half* w2m = g_W2Th + (size_t)m * H_ * H_;
    const float4* psrc0 = (const float4*)(w2m + (size_t)pn * H_) + pc;
    // src advance per iter: 32 rows * H_ halves = 32*256/8 float4 = 1024 float4

    // ---- X: issue global loads FIRST (hide LDG latency under cp.async issue) ----
    float4 xv[4];
    {
        const float* xsrc = xs + ((size_t)m * B_ + r0) * IN_;
#pragma unroll
        for (int i = 0; i < 2; ++i) {
            int idx = t + i * NTHR;            // 512 chunks of 8 halves
            int row = idx >> 3, c = idx & 7;
            const float4* p = (const float4*)(xsrc + row * IN_ + c * 8);
            xv[2 * i]     = __ldg(p);
            xv[2 * i + 1] = __ldg(p + 1);
        }
    }

    // ---- G0: W1 via cp.async ----
    {
        const float4* w1s = (const float4*)(g_W1Th + (size_t)m * H_ * IN_);
#pragma unroll
        for (int i = 0; i < 8; ++i) {          // 2048 x 16B
            int idx = t + i * NTHR;
            int row = idx >> 3, c = idx & 7;
            cpa16(sb + SM_W1 + row * 128 + ((c ^ (row & 7)) << 4), w1s + idx);
        }
    }
    CP_COMMIT();
    // ---- G1, G2: W2 chunks 0,1 -> dedicated ring slots ----
#pragma unroll
    for (int kb = 0; kb < 2; ++kb) {
        unsigned slot = kb ? SM_RING1 : SM_RING0;
#pragma unroll
        for (int i = 0; i < 8; ++i)
            cpa16(sb + slot + pdst0 + i * 4096, psrc0 + kb * 8 + i * 1024);
        CP_COMMIT();
    }

    // ---- X: convert + store fp16 to SM_X ----
    {
#pragma unroll
        for (int i = 0; i < 2; ++i) {
            int idx = t + i * NTHR;
            int row = idx >> 3, c = idx & 7;
            __half2 h0 = __floats2half2_rn(xv[2 * i].x,     xv[2 * i].y);
            __half2 h1 = __floats2half2_rn(xv[2 * i].z,     xv[2 * i].w);
            __half2 h2 = __floats2half2_rn(xv[2 * i + 1].x, xv[2 * i + 1].y);
            __half2 h3 = __floats2half2_rn(xv[2 * i + 1].z, xv[2 * i + 1].w);
            uint4 u;
            u.x = *(unsigned*)&h0; u.y = *(unsigned*)&h1;
            u.z = *(unsigned*)&h2; u.w = *(unsigned*)&h3;
            *(uint4*)(smem + SM_X + row * 128 + ((c ^ (row & 7)) << 4)) = u;
        }
    }

    // precomputed ldmatrix s=0 byte offsets
    const int rin = lane & 7, sub = lane >> 3;
    unsigned aoff0[2], boff0[4];
    {
        int bit  = sub >> 1;                 // A chunk LSB
        int roff = rin + (sub & 1) * 8;
#pragma unroll
        for (int mt = 0; mt < 2; ++mt) {
            int row = m0 + mt * 16 + roff;
            aoff0[mt] = (unsigned)(row * 128) + (((unsigned)(bit ^ (row & 7))) << 4);
        }
        bit  = sub & 1;                      // B chunk LSB
        roff = rin + (sub >> 1) * 8;
#pragma unroll
        for (int p = 0; p < 4; ++p) {
            int row = n0 + p * 16 + roff;
            boff0[p] = (unsigned)(row * 128) + (((unsigned)(bit ^ (row & 7))) << 4);
        }
    }

    float acc[2][8][4];
#pragma unroll
    for (int mt = 0; mt < 2; ++mt)
#pragma unroll
        for (int nt = 0; nt < 8; ++nt)
#pragma unroll
            for (int j = 0; j < 4; ++j) acc[mt][nt][j] = 0.f;

    // ---- layer 1: K=64, 4 k16-steps ----
    CP_WAIT(2);        // G0 (W1) done; chunks 0,1 still streaming
    __syncthreads();   // X STS visible
#pragma unroll
    for (int s = 0; s < 4; ++s)
        kstep2(sb + SM_X, sb + SM_W1, (unsigned)(s << 5), aoff0, boff0, acc);
    __syncthreads();   // all warps done reading W1 before H1 overlays it

    // ---- epilogue 1: h1 = fp16(relu(acc + b1)) -> SM_H1 (over W1) ----
#pragma unroll
    for (int nt = 0; nt < 8; ++nt) {
        int col = n0 + nt * 8 + 2 * tg;
        float2 bb = __ldg((const float2*)(b1g + m * H_ + col));
        int kseg = col >> 6;
        int ch   = (col & 63) >> 3;
        int boff = (col & 7) * 2;
#pragma unroll
        for (int mt = 0; mt < 2; ++mt) {
            float* c = acc[mt][nt];
#pragma unroll
            for (int h = 0; h < 2; ++h) {
                int row = m0 + mt * 16 + g + h * 8;
                __half2 v = __floats2half2_rn(fmaxf(c[2 * h]     + bb.x, 0.f),
                                              fmaxf(c[2 * h + 1] + bb.y, 0.f));
                *(__half2*)(smem + SM_H1 + kseg * 8192 + row * 128 +
                            ((ch ^ (row & 7)) << 4) + boff) = v;
            }
        }
    }
#pragma unroll
    for (int mt = 0; mt < 2; ++mt)
#pragma unroll
        for (int nt = 0; nt < 8; ++nt)
#pragma unroll
            for (int j = 0; j < 4; ++j) acc[mt][nt][j] = 0.f;
    __syncthreads();   // h1 visible

    // ---- layer 2: K=256 = 4 chunks of 64, 2-slot ring ----
#pragma unroll
    for (int kc = 0; kc < 4; ++kc) {
        if (kc == 0) { CP_WAIT(1); } else { CP_WAIT(0); }
        __syncthreads();   // chunk kc visible; all warps done with kc-1
        if (kc == 1 || kc == 2) {
            const int pcn = kc + 1;   // prefetch chunk kc+1 into freed slot
            unsigned slot = (pcn & 1) ? SM_RING1 : SM_RING0;
#pragma unroll
            for (int i = 0; i < 8; ++i)
                cpa16(sb + slot + pdst0 + i * 4096, psrc0 + pcn * 8 + i * 1024);
            CP_COMMIT();
        }
        unsigned Aseg = sb + SM_H1 + kc * 8192;
        unsigned Wseg = sb + ((kc & 1) ? SM_RING1 : SM_RING0);
#pragma unroll
        for (int s = 0; s < 4; ++s)
            kstep2(Aseg, Wseg, (unsigned)(s << 5), aoff0, boff0, acc);
    }

    // ---- epilogue 2: out = relu(acc + b2) . w3 + b3 ----
    {
        float part[2][2] = {{0.f, 0.f}, {0.f, 0.f}};
#pragma unroll
        for (int nt = 0; nt < 8; ++nt) {
            int col = n0 + nt * 8 + 2 * tg;
            float2 bb = __ldg((const float2*)(b2g + m * H_ + col));
            float2 ww = __ldg((const float2*)(w3g + m * H_ + col));
#pragma unroll
            for (int mt = 0; mt < 2; ++mt) {
                float* c = acc[mt][nt];
                part[mt][0] = fmaf(fmaxf(c[0] + bb.x, 0.f), ww.x, part[mt][0]);
                part[mt][0] = fmaf(fmaxf(c[1] + bb.y, 0.f), ww.y, part[mt][0]);
                part[mt][1] = fmaf(fmaxf(c[2] + bb.x, 0.f), ww.x, part[mt][1]);
                part[mt][1] = fmaf(fmaxf(c[3] + bb.y, 0.f), ww.y, part[mt][1]);
            }
        }
#pragma unroll
        for (int sfl = 1; sfl < 4; sfl <<= 1)
#pragma unroll
            for (int mt = 0; mt < 2; ++mt) {
                part[mt][0] += __shfl_xor_sync(0xffffffffu, part[mt][0], sfl);
                part[mt][1] += __shfl_xor_sync(0xffffffffu, part[mt][1], sfl);
            }
        float* red = (float*)(smem + SM_RED);   // overlays dead X region
        __syncthreads();   // everyone done with layer-2 reads before X-alias write
        if (tg == 0) {
#pragma unroll
            for (int mt = 0; mt < 2; ++mt) {
                red[(m0 + mt * 16 + g) * 4     + (wid & 3)] = part[mt][0];
                red[(m0 + mt * 16 + g + 8) * 4 + (wid & 3)] = part[mt][1];
            }
        }
        __syncthreads();
        if (t < RT) {
            const float* r = red + t * 4;
            float s = (r[0] + r[1]) + (r[2] + r[3]);
            out[(size_t)m * B_ + r0 + t] = s + __ldg(b3g + m);
        }
    }
}

// ---------------- launcher ----------------
extern "C" void kernel_launch(void* const* d_in, const int* in_sizes, int n_in,
                              void* d_out, int out_size)
{
    const float* xs = (const float*)d_in[0];
    const float* W1 = (const float*)d_in[1];
    const float* b1 = (const float*)d_in[2];
    const float* W2 = (const float*)d_in[3];
    const float* b2 = (const float*)d_in[4];
    const float* W3 = (const float*)d_in[5];
    const float* b3 = (const float*)d_in[6];
    float* out = (float*)d_out;

    void* p1 = nullptr; void* p2 = nullptr;
    cudaGetSymbolAddress(&p1, g_W1Th);
    cudaGetSymbolAddress(&p2, g_W2Th);

    // grid: x = n-tiles of 64, y = 5 (W1 ktile + 4 W2 ktiles), z = models
    transpose_cvt_all<<<dim3(H_ / 64, 5, M_), 256>>>(W1, W2, (__half*)p1, (__half*)p2);

    cudaFuncSetAttribute(mlp_mma_f16,
                         cudaFuncAttributeMaxDynamicSharedMemorySize, SM_TOT);
    dim3 grid(B_ / RT, M_);   // 64 x 64 = 4096 CTAs, 2 per SM
    mlp_mma_f16<<<grid, NTHR, SM_TOT>>>(xs, b1, b2, W3, b3, out);
}